// round 1
// baseline (speedup 1.0000x reference)
#include <cuda_runtime.h>
#include <cstdint>

#define NSAMP 256
#define EMB   120
#define DIN   64
#define MODES 16
#define NPH   8

#define PIf 3.14159265358979323846f

// Persistent scratch for V: [n][m][c] as float2 (complex), 256*16*8*8B = 256 KB
__device__ float2 g_V[NSAMP * MODES * NPH];

__device__ __forceinline__ float2 cmul(float2 a, float2 b) {
    return make_float2(a.x * b.x - a.y * b.y, a.x * b.y + a.y * b.x);
}

// ---------------------------------------------------------------------------
// Kernel A: x_emb = sigmoid(x @ W^T + b); build V[n] (16x8 complex) per sample
// One block per sample, 128 threads.
// ---------------------------------------------------------------------------
__global__ void __launch_bounds__(128) emb_v_kernel(
    const float* __restrict__ x,
    const float* __restrict__ W,
    const float* __restrict__ b,
    float* __restrict__ out_emb)
{
    const int n = blockIdx.x;
    const int t = threadIdx.x;

    __shared__ float xs[DIN];
    __shared__ float semb[EMB];
    __shared__ float4 trig[60];   // (ct, st, cp, sp) per 2x2 block

    if (t < DIN) xs[t] = x[n * DIN + t];
    __syncthreads();

    if (t < EMB) {
        float acc = b[t];
        const float* wr = W + t * DIN;
        #pragma unroll
        for (int j = 0; j < DIN; j++) acc += xs[j] * wr[j];
        float s = 1.0f / (1.0f + expf(-acc));
        semb[t] = s;
        out_emb[n * EMB + t] = s;
    }
    __syncthreads();

    if (t < 60) {
        float th = semb[2 * t]     * (0.5f * PIf);
        float ph = semb[2 * t + 1] * (2.0f * PIf);
        float st_, ct_, sp_, cp_;
        sincosf(th, &st_, &ct_);
        sincosf(ph, &sp_, &cp_);
        trig[t] = make_float4(ct_, st_, cp_, sp_);
    }
    __syncthreads();

    // Threads 0..7: propagate column c of I[:, :8] through 8 brick layers.
    if (t < NPH) {
        float2 v[MODES];
        #pragma unroll
        for (int m = 0; m < MODES; m++)
            v[m] = make_float2((m == t) ? 1.0f : 0.0f, 0.0f);

        int nbefore = 0;
        #pragma unroll
        for (int d = 0; d < 8; d++) {
            const int nb  = (d & 1) ? 7 : 8;
            const int off = (d & 1);
            #pragma unroll
            for (int k = 0; k < 8; k++) {
                if (k < nb) {
                    float4 tg = trig[nbefore + k];   // ct, st, cp, sp
                    const int r0 = off + 2 * k;
                    float2 t0 = v[r0], t1 = v[r0 + 1];
                    float2 epct = make_float2(tg.z * tg.x, tg.w * tg.x); // e^{i phi} * cos(theta)
                    float2 epst = make_float2(tg.z * tg.y, tg.w * tg.y); // e^{i phi} * sin(theta)
                    float2 n0 = cmul(epct, t0);
                    n0.x -= tg.y * t1.x;  n0.y -= tg.y * t1.y;           // - st * t1
                    float2 n1 = cmul(epst, t0);
                    n1.x += tg.x * t1.x;  n1.y += tg.x * t1.y;           // + ct * t1
                    v[r0] = n0;  v[r0 + 1] = n1;
                }
            }
            nbefore += nb;
        }
        #pragma unroll
        for (int m = 0; m < MODES; m++)
            g_V[n * (MODES * NPH) + m * NPH + t] = v[m];
    }
}

// ---------------------------------------------------------------------------
// Kernel B: for each pair (a,b): G = V[a]^H V[b] (8x8 complex), perm via
// Gray-code Ryser, K[a,b] = |perm|^2 (diag forced to 1).
// One warp per pair; block = 8 warps sharing V[a].
// Lane t handles Gray indices 8t..8t+7: inner steps flip only bits 0..2,
// whose columns are cached in registers -> near-zero inner-loop LDS.
// ---------------------------------------------------------------------------
__global__ void __launch_bounds__(256) pair_kernel(float* __restrict__ Kout)
{
    const int tid  = threadIdx.x;
    const int w    = tid >> 5;          // warp 0..7
    const int lane = tid & 31;
    const int a    = blockIdx.x >> 5;   // 0..255
    const int bg   = blockIdx.x & 31;   // 0..31
    const int bcol = bg * 8 + w;        // 0..255

    __shared__ float2 sVa[MODES * NPH];        // [m*8+i]
    __shared__ float2 sVb[8][MODES * NPH];
    __shared__ float2 sA[8][64];               // [i*8+j]

    // Load V[a] (block-wide) and V[b] (per warp)
    for (int idx = tid; idx < MODES * NPH; idx += 256)
        sVa[idx] = g_V[a * (MODES * NPH) + idx];
    #pragma unroll
    for (int r = 0; r < 4; r++)
        sVb[w][lane + r * 32] = g_V[bcol * (MODES * NPH) + lane + r * 32];
    __syncthreads();

    // G[i][j] = sum_m conj(Va[m][i]) * Vb[m][j]; lane computes 2 entries.
    #pragma unroll
    for (int e = 0; e < 2; e++) {
        const int idx = lane + e * 32;
        const int i = idx >> 3, j = idx & 7;
        float2 acc = make_float2(0.0f, 0.0f);
        #pragma unroll
        for (int m = 0; m < MODES; m++) {
            float2 va = sVa[m * 8 + i];
            float2 vb = sVb[w][m * 8 + j];
            acc.x += va.x * vb.x + va.y * vb.y;
            acc.y += va.x * vb.y - va.y * vb.x;
        }
        sA[w][idx] = acc;
    }
    __syncwarp();

    // Cache columns 0..2 in registers (used by all Gray inner steps)
    float2 cr[3][8];
    #pragma unroll
    for (int j = 0; j < 3; j++)
        #pragma unroll
        for (int i = 0; i < 8; i++)
            cr[j][i] = sA[w][i * 8 + j];

    // Initial subset: gray(8*lane) = (lane<<3) ^ (lane<<2), bits >= 2 only.
    unsigned g = (((unsigned)lane << 3) ^ ((unsigned)lane << 2)) & 0xFFu;

    float2 rs[8];
    #pragma unroll
    for (int i = 0; i < 8; i++) rs[i] = make_float2(0.0f, 0.0f);

    #pragma unroll
    for (int jb = 2; jb < 8; jb++) {
        const float msk = (float)((g >> jb) & 1u);
        #pragma unroll
        for (int i = 0; i < 8; i++) {
            float2 c = (jb == 2) ? cr[2][i] : sA[w][i * 8 + jb];
            rs[i].x += msk * c.x;
            rs[i].y += msk * c.y;
        }
    }

    float2 acc = make_float2(0.0f, 0.0f);
    const int CTZ[8] = {0, 0, 1, 0, 2, 0, 1, 0};

    #pragma unroll
    for (int k = 0; k < 8; k++) {
        if (k > 0) {
            const int jb = CTZ[k];
            g ^= (1u << jb);
            const float s = ((g >> jb) & 1u) ? 1.0f : -1.0f;
            #pragma unroll
            for (int i = 0; i < 8; i++) {
                rs[i].x += s * cr[jb][i].x;
                rs[i].y += s * cr[jb][i].y;
            }
        }
        // product of 8 complex row sums (tree for ILP)
        float2 p01 = cmul(rs[0], rs[1]);
        float2 p23 = cmul(rs[2], rs[3]);
        float2 p45 = cmul(rs[4], rs[5]);
        float2 p67 = cmul(rs[6], rs[7]);
        float2 p = cmul(cmul(p01, p23), cmul(p45, p67));
        // sign = (-1)^{popcount(subset)} ; popcount parity == (8*lane+k)&1 == k&1
        if (k & 1) { acc.x -= p.x; acc.y -= p.y; }
        else       { acc.x += p.x; acc.y += p.y; }
    }

    // Warp reduce (complex)
    #pragma unroll
    for (int off = 16; off > 0; off >>= 1) {
        acc.x += __shfl_xor_sync(0xFFFFFFFFu, acc.x, off);
        acc.y += __shfl_xor_sync(0xFFFFFFFFu, acc.y, off);
    }

    if (lane == 0) {
        float kv = (a == bcol) ? 1.0f : (acc.x * acc.x + acc.y * acc.y);
        Kout[a * NSAMP + bcol] = kv;
    }
}

// ---------------------------------------------------------------------------
extern "C" void kernel_launch(void* const* d_in, const int* in_sizes, int n_in,
                              void* d_out, int out_size)
{
    const float* x = (const float*)d_in[0];   // (256, 64)
    const float* W = (const float*)d_in[1];   // (120, 64)
    const float* b = (const float*)d_in[2];   // (120,)
    float* out = (float*)d_out;               // [x_emb (30720) | K (65536)]

    emb_v_kernel<<<NSAMP, 128>>>(x, W, b, out);
    pair_kernel<<<NSAMP * 32, 256>>>(out + NSAMP * EMB);
}

// round 3
// speedup vs baseline: 1.5719x; 1.5719x over previous
#include <cuda_runtime.h>
#include <cstdint>

#define NSAMP 256
#define EMB   120
#define DIN   64
#define MODES 16
#define NPH   8

#define PIf 3.14159265358979323846f

// Persistent scratch for V: [n][m][c] as float2 (complex), 256*16*8*8B = 256 KB
__device__ float2 g_V[NSAMP * MODES * NPH];

__device__ __forceinline__ float2 cmul(float2 a, float2 b) {
    return make_float2(a.x * b.x - a.y * b.y, a.x * b.y + a.y * b.x);
}

// ---------------------------------------------------------------------------
// Kernel A: x_emb = sigmoid(x @ W^T + b); build V[n] (16x8 complex) per sample
// One block per sample, 128 threads.
// ---------------------------------------------------------------------------
__global__ void __launch_bounds__(128) emb_v_kernel(
    const float* __restrict__ x,
    const float* __restrict__ W,
    const float* __restrict__ b,
    float* __restrict__ out_emb)
{
    const int n = blockIdx.x;
    const int t = threadIdx.x;

    __shared__ float xs[DIN];
    __shared__ float semb[EMB];
    __shared__ float4 trig[60];   // (ct, st, cp, sp) per 2x2 block

    if (t < DIN) xs[t] = x[n * DIN + t];
    __syncthreads();

    if (t < EMB) {
        float acc = b[t];
        const float* wr = W + t * DIN;
        #pragma unroll
        for (int j = 0; j < DIN; j++) acc += xs[j] * wr[j];
        float s = 1.0f / (1.0f + expf(-acc));
        semb[t] = s;
        out_emb[n * EMB + t] = s;
    }
    __syncthreads();

    if (t < 60) {
        float th = semb[2 * t]     * (0.5f * PIf);
        float ph = semb[2 * t + 1] * (2.0f * PIf);
        float st_, ct_, sp_, cp_;
        sincosf(th, &st_, &ct_);
        sincosf(ph, &sp_, &cp_);
        trig[t] = make_float4(ct_, st_, cp_, sp_);
    }
    __syncthreads();

    // Threads 0..7: propagate column c of I[:, :8] through 8 brick layers.
    if (t < NPH) {
        float2 v[MODES];
        #pragma unroll
        for (int m = 0; m < MODES; m++)
            v[m] = make_float2((m == t) ? 1.0f : 0.0f, 0.0f);

        int nbefore = 0;
        #pragma unroll
        for (int d = 0; d < 8; d++) {
            const int nb  = (d & 1) ? 7 : 8;
            const int off = (d & 1);
            #pragma unroll
            for (int k = 0; k < 8; k++) {
                if (k < nb) {
                    float4 tg = trig[nbefore + k];   // ct, st, cp, sp
                    const int r0 = off + 2 * k;
                    float2 t0 = v[r0], t1 = v[r0 + 1];
                    float2 epct = make_float2(tg.z * tg.x, tg.w * tg.x); // e^{i phi} cos
                    float2 epst = make_float2(tg.z * tg.y, tg.w * tg.y); // e^{i phi} sin
                    float2 n0 = cmul(epct, t0);
                    n0.x -= tg.y * t1.x;  n0.y -= tg.y * t1.y;
                    float2 n1 = cmul(epst, t0);
                    n1.x += tg.x * t1.x;  n1.y += tg.x * t1.y;
                    v[r0] = n0;  v[r0 + 1] = n1;
                }
            }
            nbefore += nb;
        }
        #pragma unroll
        for (int m = 0; m < MODES; m++)
            g_V[n * (MODES * NPH) + m * NPH + t] = v[m];
    }
}

// ---------------------------------------------------------------------------
// Kernel B (triangular): K is exactly symmetric (perm(A^H) = conj perm(A)),
// so compute only macro-tiles (qa, bg) with bg >= qa; 528 tiles x 8 blocks.
// One warp per pair (a, b); writes K[a,b] and K[b,a]. Diagonal = 1.0.
// ---------------------------------------------------------------------------
__global__ void __launch_bounds__(256) pair_kernel_tri(float* __restrict__ Kout)
{
    const int tid  = threadIdx.x;
    const int w    = tid >> 5;          // warp 0..7
    const int lane = tid & 31;

    // Decode macro-tile: t in [0,528) -> (bg, qa) with qa <= bg
    const int tIdx = blockIdx.x >> 3;
    const int ai   = blockIdx.x & 7;
    int bg = (int)((sqrtf(8.0f * (float)tIdx + 1.0f) - 1.0f) * 0.5f);
    if ((bg + 1) * (bg + 2) / 2 <= tIdx) bg++;
    if (bg * (bg + 1) / 2 > tIdx) bg--;
    const int qa   = tIdx - bg * (bg + 1) / 2;
    const int a    = qa * 8 + ai;       // 0..255
    const int bcol = bg * 8 + w;        // 0..255, bcol >= qa*8

    __shared__ float2 sVa[MODES * NPH];        // [m*8+i]
    __shared__ float2 sVb[8][MODES * NPH];
    __shared__ float2 sA[8][64];               // [i*8+j]

    // Load V[a] (block-wide) and V[b] (per warp)
    for (int idx = tid; idx < MODES * NPH; idx += 256)
        sVa[idx] = g_V[a * (MODES * NPH) + idx];
    #pragma unroll
    for (int r = 0; r < 4; r++)
        sVb[w][lane + r * 32] = g_V[bcol * (MODES * NPH) + lane + r * 32];
    __syncthreads();

    if (bcol < a) return;                       // below diagonal: mirror handles it
    if (bcol == a) {                            // diagonal forced to 1.0
        if (lane == 0) Kout[a * NSAMP + a] = 1.0f;
        return;
    }

    // G[i][j] = sum_m conj(Va[m][i]) * Vb[m][j]; lane computes 2 entries.
    #pragma unroll
    for (int e = 0; e < 2; e++) {
        const int idx = lane + e * 32;
        const int i = idx >> 3, j = idx & 7;
        float2 acc = make_float2(0.0f, 0.0f);
        #pragma unroll
        for (int m = 0; m < MODES; m++) {
            float2 va = sVa[m * 8 + i];
            float2 vb = sVb[w][m * 8 + j];
            acc.x += va.x * vb.x + va.y * vb.y;
            acc.y += va.x * vb.y - va.y * vb.x;
        }
        sA[w][idx] = acc;
    }
    __syncwarp();

    // Cache columns 0..1 in registers (bits 0/1 flip 6 of 7 inner Gray steps).
    // Column 2 (flips once per 8 steps) stays in shared: broadcast LDS, and
    // dropping it saves 16 registers -> occupancy 33% -> 50%.
    float2 cr[2][8];
    #pragma unroll
    for (int j = 0; j < 2; j++)
        #pragma unroll
        for (int i = 0; i < 8; i++)
            cr[j][i] = sA[w][i * 8 + j];

    // Initial subset: gray(8*lane) = (lane<<3) ^ (lane<<2), bits >= 2 only.
    unsigned g = (((unsigned)lane << 3) ^ ((unsigned)lane << 2)) & 0xFFu;

    float2 rs[8];
    #pragma unroll
    for (int i = 0; i < 8; i++) rs[i] = make_float2(0.0f, 0.0f);

    #pragma unroll
    for (int jb = 2; jb < 8; jb++) {
        const float msk = (float)((g >> jb) & 1u);
        #pragma unroll
        for (int i = 0; i < 8; i++) {
            float2 c = sA[w][i * 8 + jb];
            rs[i].x += msk * c.x;
            rs[i].y += msk * c.y;
        }
    }

    float2 acc = make_float2(0.0f, 0.0f);
    const int CTZ[8] = {0, 0, 1, 0, 2, 0, 1, 0};

    #pragma unroll
    for (int k = 0; k < 8; k++) {
        if (k > 0) {
            const int jb = CTZ[k];
            g ^= (1u << jb);
            const float s = ((g >> jb) & 1u) ? 1.0f : -1.0f;
            if (jb < 2) {
                #pragma unroll
                for (int i = 0; i < 8; i++) {
                    rs[i].x += s * cr[jb][i].x;
                    rs[i].y += s * cr[jb][i].y;
                }
            } else {
                #pragma unroll
                for (int i = 0; i < 8; i++) {
                    float2 c = sA[w][i * 8 + 2];
                    rs[i].x += s * c.x;
                    rs[i].y += s * c.y;
                }
            }
        }
        // product of 8 complex row sums (tree for ILP)
        float2 p01 = cmul(rs[0], rs[1]);
        float2 p23 = cmul(rs[2], rs[3]);
        float2 p45 = cmul(rs[4], rs[5]);
        float2 p67 = cmul(rs[6], rs[7]);
        float2 p = cmul(cmul(p01, p23), cmul(p45, p67));
        // sign = (-1)^{popcount(subset)}; parity(gray(8*lane+k)) == k&1
        if (k & 1) { acc.x -= p.x; acc.y -= p.y; }
        else       { acc.x += p.x; acc.y += p.y; }
    }

    // Warp reduce (complex)
    #pragma unroll
    for (int off = 16; off > 0; off >>= 1) {
        acc.x += __shfl_xor_sync(0xFFFFFFFFu, acc.x, off);
        acc.y += __shfl_xor_sync(0xFFFFFFFFu, acc.y, off);
    }

    if (lane == 0) {
        float kv = acc.x * acc.x + acc.y * acc.y;
        Kout[a * NSAMP + bcol] = kv;
        Kout[bcol * NSAMP + a] = kv;
    }
}

// ---------------------------------------------------------------------------
extern "C" void kernel_launch(void* const* d_in, const int* in_sizes, int n_in,
                              void* d_out, int out_size)
{
    const float* x = (const float*)d_in[0];   // (256, 64)
    const float* W = (const float*)d_in[1];   // (120, 64)
    const float* b = (const float*)d_in[2];   // (120,)
    float* out = (float*)d_out;               // [x_emb (30720) | K (65536)]

    emb_v_kernel<<<NSAMP, 128>>>(x, W, b, out);
    pair_kernel_tri<<<528 * 8, 256>>>(out + NSAMP * EMB);
}